// round 2
// baseline (speedup 1.0000x reference)
#include <cuda_runtime.h>
#include <cuda_bf16.h>
#include <cstdint>

// Problem constants
#define BB 4
#define SS 2048
#define DD 1024
#define NH 4
#define DH 256
#define NSEQ (BB*NH)          // 16 independent (b,h) sequences
#define CLN 8                 // CTAs per cluster in scan

// ---------------------------------------------------------------------------
// Scratch (device globals — no runtime allocation allowed)
// ---------------------------------------------------------------------------
__device__ float d_xconv[(size_t)BB*SS*DD];                // 33.5 MB
__device__ float d_G[(size_t)BB*NH*SS*4*DH];               // 134 MB  gates+rec_bias, layout [cid][s][g*256+e]
__device__ float d_ys[(size_t)BB*NH*SS*DH];                // 33.5 MB raw y before groupnorm

// ---------------------------------------------------------------------------
// f32x2 + cluster helpers
// ---------------------------------------------------------------------------
__device__ __forceinline__ unsigned long long pack2(float lo, float hi) {
    unsigned long long d;
    asm("mov.b64 %0, {%1,%2};" : "=l"(d) : "f"(lo), "f"(hi));
    return d;
}
__device__ __forceinline__ unsigned long long fma2(unsigned long long a,
                                                   unsigned long long b,
                                                   unsigned long long c) {
    unsigned long long d;
    asm("fma.rn.f32x2 %0, %1, %2, %3;" : "=l"(d) : "l"(a), "l"(b), "l"(c));
    return d;
}
__device__ __forceinline__ void unpack2(unsigned long long d, float& lo, float& hi) {
    asm("mov.b64 {%0,%1}, %2;" : "=f"(lo), "=f"(hi) : "l"(d));
}
__device__ __forceinline__ uint32_t smem_u32(const void* p) {
    uint32_t a;
    asm("{ .reg .u64 t; cvta.to.shared.u64 t, %1; cvt.u32.u64 %0, t; }"
        : "=r"(a) : "l"(p));
    return a;
}
__device__ __forceinline__ void cluster_barrier() {
    asm volatile("barrier.cluster.arrive.aligned;" ::: "memory");
    asm volatile("barrier.cluster.wait.aligned;"   ::: "memory");
}
__device__ __forceinline__ void st_remote_f32(uint32_t local_addr, uint32_t rank, float v) {
    uint32_t ra;
    asm("mapa.shared::cluster.u32 %0, %1, %2;" : "=r"(ra) : "r"(local_addr), "r"(rank));
    asm volatile("st.shared::cluster.f32 [%0], %1;" :: "r"(ra), "f"(v) : "memory");
}
__device__ __forceinline__ void mbar_arrive_remote(uint32_t local_mbar, uint32_t rank) {
    uint32_t ra;
    asm("mapa.shared::cluster.u32 %0, %1, %2;" : "=r"(ra) : "r"(local_mbar), "r"(rank));
    asm volatile("mbarrier.arrive.release.cluster.shared::cluster.b64 _, [%0];"
                 :: "r"(ra) : "memory");
}
__device__ __forceinline__ void mbar_wait_cluster(uint32_t mbar, uint32_t parity) {
    uint32_t done;
    asm volatile(
        "{\n\t.reg .pred P;\n\t"
        "mbarrier.try_wait.parity.acquire.cluster.shared::cta.b64 P, [%1], %2, 0x989680;\n\t"
        "selp.b32 %0, 1, 0, P;\n\t}"
        : "=r"(done) : "r"(mbar), "r"(parity) : "memory");
    while (!done) {
        asm volatile(
            "{\n\t.reg .pred P;\n\t"
            "mbarrier.try_wait.parity.acquire.cluster.shared::cta.b64 P, [%1], %2, 0x989680;\n\t"
            "selp.b32 %0, 1, 0, P;\n\t}"
            : "=r"(done) : "r"(mbar), "r"(parity) : "memory");
    }
}

// ---------------------------------------------------------------------------
// Kernel 1: causal depthwise conv (K=4) + swish
// ---------------------------------------------------------------------------
__global__ void conv_swish_kernel(const float* __restrict__ x,
                                  const float* __restrict__ ck,
                                  const float* __restrict__ cb) {
    size_t idx = (size_t)blockIdx.x * blockDim.x + threadIdx.x;
    size_t total = (size_t)BB * SS * DD;
    if (idx >= total) return;
    int d = idx & (DD - 1);
    size_t bs = idx >> 10;
    int s = (int)(bs & (SS - 1));
    size_t b = bs >> 11;
    float acc = cb[d];
    const float* xb = x + b * (size_t)SS * DD + d;
#pragma unroll
    for (int k = 0; k < 4; k++) {
        int ss = s + k - 3;
        if (ss >= 0) acc = fmaf(xb[(size_t)ss * DD], ck[k * DD + d], acc);
    }
    float sig = 1.0f / (1.0f + __expf(-acc));
    d_xconv[idx] = acc * sig;
}

// ---------------------------------------------------------------------------
// Kernel 2: gate GEMMs (fp32, f32x2 FMA), smem double-buffered.
// Writes d_G[((b*NH+h)*S + s)*1024 + g*256 + e]  (rec_bias folded in)
// ---------------------------------------------------------------------------
#define BM 64
#define BN 64
#define BK 16

__global__ __launch_bounds__(256)
void gemm_gates_kernel(const float* __restrict__ x,
                       const float* __restrict__ w_i, const float* __restrict__ w_f,
                       const float* __restrict__ w_z, const float* __restrict__ w_o,
                       const float* __restrict__ rec_bias) {
    __shared__ float As[2][BK][BM + 4];
    __shared__ float Bs[2][BK][BN + 8];

    int bx = blockIdx.x;
    int hg  = bx >> 9;           // 0..15
    int rem = bx & 511;
    int mt  = rem >> 2;          // 0..127
    int nt  = rem & 3;           // 0..3
    int h = hg >> 2, g = hg & 3;

    const float* A = (g < 2) ? d_xconv : x;
    const float* W = (g == 0) ? w_i : (g == 1) ? w_f : (g == 2) ? w_z : w_o;
    W += (size_t)h * DH * DH;
    int acol = h * DH;

    int tid = threadIdx.x;
    int a_m  = tid >> 2;               // 0..63
    int a_k4 = (tid & 3) << 2;         // 0,4,8,12
    int b_k  = tid >> 4;               // 0..15
    int b_n4 = (tid & 15) << 2;        // 0..60
    int ty = tid >> 4, tx = tid & 15;  // 16 x 16 threads, 4x4 micro-tile

    int m0 = mt * BM;
    const float* Aptr = A + (size_t)(m0 + a_m) * DD + acol + a_k4;
    const float* Wptr = W + (size_t)b_k * DH + nt * BN + b_n4;

    unsigned long long acc[4][2];
#pragma unroll
    for (int i = 0; i < 4; i++) { acc[i][0] = 0ULL; acc[i][1] = 0ULL; }

    // prime buffer 0
    {
        float4 av = *(const float4*)(Aptr);
        float4 bv = *(const float4*)(Wptr);
        As[0][a_k4 + 0][a_m] = av.x;
        As[0][a_k4 + 1][a_m] = av.y;
        As[0][a_k4 + 2][a_m] = av.z;
        As[0][a_k4 + 3][a_m] = av.w;
        *(float4*)&Bs[0][b_k][b_n4] = bv;
    }
    __syncthreads();

    int buf = 0;
    for (int k0 = 0; k0 < DH; k0 += BK) {
        bool more = (k0 + BK) < DH;
        float4 avn, bvn;
        if (more) {
            avn = *(const float4*)(Aptr + k0 + BK);
            bvn = *(const float4*)(Wptr + (size_t)(k0 + BK) * DH);
        }
#pragma unroll
        for (int k = 0; k < BK; k++) {
            float4 a4 = *(const float4*)&As[buf][k][ty * 4];
            float4 b4 = *(const float4*)&Bs[buf][k][tx * 4];
            unsigned long long b01 = pack2(b4.x, b4.y);
            unsigned long long b23 = pack2(b4.z, b4.w);
            float ar[4] = {a4.x, a4.y, a4.z, a4.w};
#pragma unroll
            for (int i = 0; i < 4; i++) {
                unsigned long long ad = pack2(ar[i], ar[i]);
                acc[i][0] = fma2(ad, b01, acc[i][0]);
                acc[i][1] = fma2(ad, b23, acc[i][1]);
            }
        }
        if (more) {
            int nb = buf ^ 1;
            As[nb][a_k4 + 0][a_m] = avn.x;
            As[nb][a_k4 + 1][a_m] = avn.y;
            As[nb][a_k4 + 2][a_m] = avn.z;
            As[nb][a_k4 + 3][a_m] = avn.w;
            *(float4*)&Bs[nb][b_k][b_n4] = bvn;
        }
        __syncthreads();
        buf ^= 1;
    }

    int n = nt * BN + tx * 4;                     // e in 0..255
    const float* rb = rec_bias + (g * NH + h) * DH + n;
    float rb0 = rb[0], rb1 = rb[1], rb2 = rb[2], rb3 = rb[3];
#pragma unroll
    for (int i = 0; i < 4; i++) {
        int m = m0 + ty * 4 + i;
        int b = m >> 11;                // m / S
        int s = m & (SS - 1);
        float o0, o1, o2, o3;
        unpack2(acc[i][0], o0, o1);
        unpack2(acc[i][1], o2, o3);
        float4 outv = make_float4(o0 + rb0, o1 + rb1, o2 + rb2, o3 + rb3);
        size_t gidx = (((size_t)(b * NH + h) * SS + s) << 10) + g * DH + n;
        *(float4*)&d_G[gidx] = outv;
    }
}

// ---------------------------------------------------------------------------
// Kernel 3: sequential sLSTM scan, v2.
// 8-CTA cluster per (b,h), 256 threads per CTA.
// CTA c owns e in [c*32, c*32+32) for ALL 4 gates -> update is CTA-local.
// Thread (w = tid>>5, l = tid&31): gate g = w&3, d-half = w>>2, e = c*32+l.
// Weights in registers as f32x2 pairs (64 ull/thread = 128 d-values).
// Per step:
//   matvec (fma2, warp-uniform broadcast LDS of y)
//   -> STS partial[half][g*32+l] (+gate input on half 0), __syncthreads
//   -> warp 0: combine 4 gates, fast-math cell update (32 e's),
//      push y to all 8 CTAs' y buffer (double-buffered) via st.shared::cluster,
//      release-arrive on all 8 CTAs' mbarriers
//   -> all threads: acquire-wait on local mbarrier (8 arrivals), flip parity.
// ---------------------------------------------------------------------------
__global__ void __launch_bounds__(256, 1) __cluster_dims__(CLN, 1, 1)
scan_kernel(const float* __restrict__ rk) {
    __shared__ __align__(16) float y2[2][DH];
    __shared__ float part[2][128];
    __shared__ __align__(8) unsigned long long mbar;

    int tid = threadIdx.x;
    int w = tid >> 5, l = tid & 31;
    int g = w & 3, half = w >> 2;
    int c   = blockIdx.x & (CLN - 1);
    int cid = blockIdx.x >> 3;              // b*NH + h
    int h   = cid & (NH - 1);
    int e   = c * 32 + l;
    int slot = g * 32 + l;

    // ---- load this thread's 128 recurrent weights as 64 f32x2 pairs ----
    // rec_kernel layout: rk[((h*DH + d)*4 + g)*DH + e], d in [half*128, half*128+128)
    unsigned long long wv[64];
    {
        const float* wp = rk + (((size_t)h * DH + half * 128) * 4 + g) * DH + e;
#pragma unroll
        for (int j = 0; j < 64; j++) {
            float lo = wp[(size_t)(2 * j)     * 4 * DH];
            float hi = wp[(size_t)(2 * j + 1) * 4 * DH];
            wv[j] = pack2(lo, hi);
        }
    }

    // zero both y buffers
    {
        float* yz = &y2[0][0];
        yz[tid] = 0.0f;
        yz[tid + 256] = 0.0f;
    }
    if (tid == 0) {
        uint32_t mb = smem_u32(&mbar);
        asm volatile("mbarrier.init.shared.b64 [%0], %1;" :: "r"(mb), "r"(CLN) : "memory");
    }
    __syncthreads();
    cluster_barrier();   // all mbarriers + zeroed y visible cluster-wide

    const float* gptr = d_G + (size_t)cid * SS * 1024 + g * 256 + c * 32 + l;
    float g_cur = (half == 0) ? __ldcg(gptr) : 0.0f;

    float c_st = 0.0f, n_st = 0.0f, m_st = 0.0f;
    float* ysb = d_ys + (size_t)cid * SS * DH;

    uint32_t ybase = smem_u32(&y2[0][0]);
    uint32_t mb    = smem_u32(&mbar);

    uint32_t par = 0;
    for (int s = 0; s < SS; s++) {
        // prefetch next step's gate input (one full step of slack vs DRAM)
        float g_nxt = 0.0f;
        if (half == 0 && s + 1 < SS) g_nxt = __ldcg(gptr + (size_t)(s + 1) * 1024);

        // ---- matvec: 64 fma2 over this thread's 128 d-values ----
        uint32_t yb = ybase + (uint32_t)(((s & 1) * DH + half * 128) * 4);
        unsigned long long a0 = 0ULL, a1 = 0ULL;
#pragma unroll
        for (int j = 0; j < 32; j++) {
            unsigned long long p0, p1;
            asm("ld.shared.v2.u64 {%0,%1}, [%2];"
                : "=l"(p0), "=l"(p1) : "r"(yb + j * 16));
            a0 = fma2(p0, wv[2 * j],     a0);
            a1 = fma2(p1, wv[2 * j + 1], a1);
        }
        float s0, s1, s2, s3;
        unpack2(a0, s0, s1);
        unpack2(a1, s2, s3);
        float partsum = (s0 + s1) + (s2 + s3);
        if (half == 0) partsum += g_cur;
        part[half][slot] = partsum;
        g_cur = g_nxt;
        __syncthreads();

        if (w == 0) {
            float ir  = part[0][l]      + part[1][l];
            float fr  = part[0][32 + l] + part[1][32 + l];
            float zr  = part[0][64 + l] + part[1][64 + l];
            float orr = part[0][96 + l] + part[1][96 + l];
            // log_sigmoid(fr) = min(fr,0) - log1p(exp(-|fr|))
            float ls  = fminf(fr, 0.0f) - __logf(1.0f + __expf(-fabsf(fr)));
            float lfm = m_st + ls;
            float mn  = fmaxf(ir, lfm);
            float ig  = __expf(ir - mn);
            float fg  = __expf(lfm - mn);
            float tz  = 1.0f - 2.0f * __fdividef(1.0f, __expf(2.0f * zr) + 1.0f);
            c_st = fg * c_st + ig * tz;
            n_st = fg * n_st + ig;
            m_st = mn;
            float sg = __fdividef(1.0f, 1.0f + __expf(-orr));
            float yv = sg * __fdividef(c_st, n_st);

            // push y to all 8 CTAs' next-parity buffer
            uint32_t la = ybase + (uint32_t)((((s + 1) & 1) * DH + e) * 4);
#pragma unroll
            for (int r = 0; r < CLN; r++) st_remote_f32(la, (uint32_t)r, yv);
            ysb[(size_t)s * DH + e] = yv;

            __syncwarp();
            if (l == 0) {
#pragma unroll
                for (int r = 0; r < CLN; r++) mbar_arrive_remote(mb, (uint32_t)r);
            }
        }

        mbar_wait_cluster(mb, par);
        par ^= 1;
    }
    cluster_barrier();
}

// ---------------------------------------------------------------------------
// Kernel 4: per-(b,h,s) GroupNorm over DH=256 + affine, write final output.
// ---------------------------------------------------------------------------
__global__ __launch_bounds__(256)
void groupnorm_kernel(const float* __restrict__ gn_scale,
                      const float* __restrict__ gn_bias,
                      float* __restrict__ out) {
    __shared__ float red_s[8];
    __shared__ float red_q[8];
    __shared__ float mu_sh, rs_sh;

    int row = blockIdx.x;              // cid*S + s
    int e   = threadIdx.x;
    int cid = row >> 11;
    int s   = row & (SS - 1);
    int b = cid >> 2, h = cid & 3;

    float v = d_ys[(size_t)row * DH + e];
    float sv = v, sq = v * v;
#pragma unroll
    for (int off = 16; off > 0; off >>= 1) {
        sv += __shfl_down_sync(0xFFFFFFFFu, sv, off);
        sq += __shfl_down_sync(0xFFFFFFFFu, sq, off);
    }
    int warp = e >> 5, lane = e & 31;
    if (lane == 0) { red_s[warp] = sv; red_q[warp] = sq; }
    __syncthreads();
    if (e == 0) {
        float ts = 0.f, tq = 0.f;
#pragma unroll
        for (int i = 0; i < 8; i++) { ts += red_s[i]; tq += red_q[i]; }
        float mu  = ts * (1.0f / DH);
        float var = tq * (1.0f / DH) - mu * mu;
        mu_sh = mu;
        rs_sh = rsqrtf(var + 1e-6f);
    }
    __syncthreads();
    int d = h * DH + e;
    float yn = (v - mu_sh) * rs_sh;
    out[((size_t)b * SS + s) * DD + d] = yn * gn_scale[d] + gn_bias[d];
}

// ---------------------------------------------------------------------------
// Launch
// Inputs (metadata order): x, conv_kernel, conv_bias, w_i, w_f, w_z, w_o,
//                          rec_kernel, rec_bias, gn_scale, gn_bias
// ---------------------------------------------------------------------------
extern "C" void kernel_launch(void* const* d_in, const int* in_sizes, int n_in,
                              void* d_out, int out_size) {
    const float* x        = (const float*)d_in[0];
    const float* convk    = (const float*)d_in[1];
    const float* convb    = (const float*)d_in[2];
    const float* w_i      = (const float*)d_in[3];
    const float* w_f      = (const float*)d_in[4];
    const float* w_z      = (const float*)d_in[5];
    const float* w_o      = (const float*)d_in[6];
    const float* rec_k    = (const float*)d_in[7];
    const float* rec_b    = (const float*)d_in[8];
    const float* gn_scale = (const float*)d_in[9];
    const float* gn_bias  = (const float*)d_in[10];
    float* out = (float*)d_out;

    size_t total = (size_t)BB * SS * DD;
    conv_swish_kernel<<<(unsigned)((total + 255) / 256), 256>>>(x, convk, convb);

    gemm_gates_kernel<<<16 * 128 * 4, 256>>>(x, w_i, w_f, w_z, w_o, rec_b);

    scan_kernel<<<NSEQ * CLN, 256>>>(rec_k);

    groupnorm_kernel<<<BB * NH * SS, 256>>>(gn_scale, gn_bias, out);
}

// round 15
// speedup vs baseline: 1.7690x; 1.7690x over previous
#include <cuda_runtime.h>
#include <cuda_bf16.h>
#include <cstdint>

// Problem constants
#define BB 4
#define SS 2048
#define DD 1024
#define NH 4
#define DH 256
#define NSEQ (BB*NH)          // 16 independent (b,h) sequences
#define CLN 8                 // CTAs per cluster in scan

// ---------------------------------------------------------------------------
// Scratch (device globals — no runtime allocation allowed)
// ---------------------------------------------------------------------------
__device__ float d_xconv[(size_t)BB*SS*DD];                // 33.5 MB
__device__ float d_G[(size_t)BB*NH*SS*4*DH];               // 134 MB  gates+rec_bias, [cid][s][g*256+e]
__device__ float d_ys[(size_t)BB*NH*SS*DH];                // 33.5 MB raw y before groupnorm
__device__ float d_st_y[NSEQ*DH];                          // scan state handoff
__device__ float d_st_c[NSEQ*DH];
__device__ float d_st_n[NSEQ*DH];
__device__ float d_st_m[NSEQ*DH];

// ---------------------------------------------------------------------------
// f32x2 + cluster helpers
// ---------------------------------------------------------------------------
__device__ __forceinline__ unsigned long long pack2(float lo, float hi) {
    unsigned long long d;
    asm("mov.b64 %0, {%1,%2};" : "=l"(d) : "f"(lo), "f"(hi));
    return d;
}
__device__ __forceinline__ unsigned long long fma2(unsigned long long a,
                                                   unsigned long long b,
                                                   unsigned long long c) {
    unsigned long long d;
    asm("fma.rn.f32x2 %0, %1, %2, %3;" : "=l"(d) : "l"(a), "l"(b), "l"(c));
    return d;
}
__device__ __forceinline__ void unpack2(unsigned long long d, float& lo, float& hi) {
    asm("mov.b64 {%0,%1}, %2;" : "=f"(lo), "=f"(hi) : "l"(d));
}
__device__ __forceinline__ uint32_t smem_u32(const void* p) {
    uint32_t a;
    asm("{ .reg .u64 t; cvta.to.shared.u64 t, %1; cvt.u32.u64 %0, t; }"
        : "=r"(a) : "l"(p));
    return a;
}
// v1-proven cluster barrier (arrive + wait, aligned)
__device__ __forceinline__ void cluster_barrier() {
    asm volatile("barrier.cluster.arrive.aligned;" ::: "memory");
    asm volatile("barrier.cluster.wait.aligned;"   ::: "memory");
}
__device__ __forceinline__ uint32_t mapa_rank(uint32_t local_addr, uint32_t rank) {
    uint32_t ra;
    asm("mapa.shared::cluster.u32 %0, %1, %2;" : "=r"(ra) : "r"(local_addr), "r"(rank));
    return ra;
}
__device__ __forceinline__ float ld_cluster_f32_addr(uint32_t remote_addr) {
    float v;
    asm volatile("ld.shared::cluster.f32 %0, [%1];" : "=f"(v) : "r"(remote_addr));
    return v;
}

// ---------------------------------------------------------------------------
// Kernel 1: causal depthwise conv (K=4) + swish
// ---------------------------------------------------------------------------
__global__ void conv_swish_kernel(const float* __restrict__ x,
                                  const float* __restrict__ ck,
                                  const float* __restrict__ cb) {
    size_t idx = (size_t)blockIdx.x * blockDim.x + threadIdx.x;
    size_t total = (size_t)BB * SS * DD;
    if (idx >= total) return;
    int d = idx & (DD - 1);
    size_t bs = idx >> 10;
    int s = (int)(bs & (SS - 1));
    size_t b = bs >> 11;
    float acc = cb[d];
    const float* xb = x + b * (size_t)SS * DD + d;
#pragma unroll
    for (int k = 0; k < 4; k++) {
        int ss = s + k - 3;
        if (ss >= 0) acc = fmaf(xb[(size_t)ss * DD], ck[k * DD + d], acc);
    }
    float sig = 1.0f / (1.0f + __expf(-acc));
    d_xconv[idx] = acc * sig;
}

// ---------------------------------------------------------------------------
// Kernel 2: gate GEMMs (fp32, f32x2 FMA), smem double-buffered.
// ---------------------------------------------------------------------------
#define BM 64
#define BN 64
#define BK 16

__global__ __launch_bounds__(256)
void gemm_gates_kernel(const float* __restrict__ x,
                       const float* __restrict__ w_i, const float* __restrict__ w_f,
                       const float* __restrict__ w_z, const float* __restrict__ w_o,
                       const float* __restrict__ rec_bias) {
    __shared__ float As[2][BK][BM + 4];
    __shared__ float Bs[2][BK][BN + 8];

    int bx = blockIdx.x;
    int hg  = bx >> 9;           // 0..15
    int rem = bx & 511;
    int mt  = rem >> 2;          // 0..127
    int nt  = rem & 3;           // 0..3
    int h = hg >> 2, g = hg & 3;

    const float* A = (g < 2) ? d_xconv : x;
    const float* W = (g == 0) ? w_i : (g == 1) ? w_f : (g == 2) ? w_z : w_o;
    W += (size_t)h * DH * DH;
    int acol = h * DH;

    int tid = threadIdx.x;
    int a_m  = tid >> 2;
    int a_k4 = (tid & 3) << 2;
    int b_k  = tid >> 4;
    int b_n4 = (tid & 15) << 2;
    int ty = tid >> 4, tx = tid & 15;

    int m0 = mt * BM;
    const float* Aptr = A + (size_t)(m0 + a_m) * DD + acol + a_k4;
    const float* Wptr = W + (size_t)b_k * DH + nt * BN + b_n4;

    unsigned long long acc[4][2];
#pragma unroll
    for (int i = 0; i < 4; i++) { acc[i][0] = 0ULL; acc[i][1] = 0ULL; }

    {
        float4 av = *(const float4*)(Aptr);
        float4 bv = *(const float4*)(Wptr);
        As[0][a_k4 + 0][a_m] = av.x;
        As[0][a_k4 + 1][a_m] = av.y;
        As[0][a_k4 + 2][a_m] = av.z;
        As[0][a_k4 + 3][a_m] = av.w;
        *(float4*)&Bs[0][b_k][b_n4] = bv;
    }
    __syncthreads();

    int buf = 0;
    for (int k0 = 0; k0 < DH; k0 += BK) {
        bool more = (k0 + BK) < DH;
        float4 avn, bvn;
        if (more) {
            avn = *(const float4*)(Aptr + k0 + BK);
            bvn = *(const float4*)(Wptr + (size_t)(k0 + BK) * DH);
        }
#pragma unroll
        for (int k = 0; k < BK; k++) {
            float4 a4 = *(const float4*)&As[buf][k][ty * 4];
            float4 b4 = *(const float4*)&Bs[buf][k][tx * 4];
            unsigned long long b01 = pack2(b4.x, b4.y);
            unsigned long long b23 = pack2(b4.z, b4.w);
            float ar[4] = {a4.x, a4.y, a4.z, a4.w};
#pragma unroll
            for (int i = 0; i < 4; i++) {
                unsigned long long ad = pack2(ar[i], ar[i]);
                acc[i][0] = fma2(ad, b01, acc[i][0]);
                acc[i][1] = fma2(ad, b23, acc[i][1]);
            }
        }
        if (more) {
            int nb = buf ^ 1;
            As[nb][a_k4 + 0][a_m] = avn.x;
            As[nb][a_k4 + 1][a_m] = avn.y;
            As[nb][a_k4 + 2][a_m] = avn.z;
            As[nb][a_k4 + 3][a_m] = avn.w;
            *(float4*)&Bs[nb][b_k][b_n4] = bvn;
        }
        __syncthreads();
        buf ^= 1;
    }

    int n = nt * BN + tx * 4;
    const float* rb = rec_bias + (g * NH + h) * DH + n;
    float rb0 = rb[0], rb1 = rb[1], rb2 = rb[2], rb3 = rb[3];
#pragma unroll
    for (int i = 0; i < 4; i++) {
        int m = m0 + ty * 4 + i;
        int b = m >> 11;
        int s = m & (SS - 1);
        float o0, o1, o2, o3;
        unpack2(acc[i][0], o0, o1);
        unpack2(acc[i][1], o2, o3);
        float4 outv = make_float4(o0 + rb0, o1 + rb1, o2 + rb2, o3 + rb3);
        size_t gidx = (((size_t)(b * NH + h) * SS + s) << 10) + g * DH + n;
        *(float4*)&d_G[gidx] = outv;
    }
}

// ---------------------------------------------------------------------------
// Kernel 3: sequential sLSTM scan, v6 = v5 with the matvec load fix.
// The y_s loads are PLAIN C++ ulonglong2 loads (not raw asm): they are
// properly ordered against __syncthreads' memory clobber, so the compiler
// cannot hoist them out of the step loop (the bug that poisoned v3/v5).
// 8-CTA cluster per (b,h), 512 threads.
// CTA c owns raw outputs o in [c*128, c*128+128), o = g*256+e.
// Per step (v1-proven ordering):
//   matvec (fma2) -> STS partial -> __syncthreads
//   -> tid<128: raw = sum partials + gate -> rawbuf[par]; prefetch next gate
//   -> cluster_barrier (arrive+wait)
//   -> tid<256: batched pulls via ld.shared::cluster, fast-math update,
//      y_s store; rank 0 stores y to gmem -> __syncthreads; flip parity.
// ---------------------------------------------------------------------------
__global__ void __launch_bounds__(512, 1) __cluster_dims__(CLN, 1, 1)
scan_kernel(const float* __restrict__ rk, int s0, int s1, int init) {
    __shared__ __align__(16) float y_s[DH];
    __shared__ float partial[4][128];
    __shared__ float rawbuf[2][128];

    int tid = threadIdx.x;
    int c   = blockIdx.x & (CLN - 1);
    int cid = blockIdx.x >> 3;              // b*NH + h
    int h   = cid & (NH - 1);

    int o_local = tid & 127;
    int sub     = tid >> 7;                 // 0..3
    int o  = c * 128 + o_local;
    int g  = o >> 8;
    int eo = o & 255;

    // ---- 64 weights as 32 f32x2 pairs: d in [sub*64, sub*64+64) ----
    unsigned long long wv[32];
    {
        const float* wp = rk + (((size_t)h * DH + sub * 64) * 4 + g) * DH + eo;
#pragma unroll
        for (int k = 0; k < 32; k++) {
            float lo = __ldcg(wp + (size_t)(2 * k)     * 4 * DH);
            float hi = __ldcg(wp + (size_t)(2 * k + 1) * 4 * DH);
            wv[k] = pack2(lo, hi);
        }
    }

    float c_st = 0.0f, n_st = 0.0f, m_st = 0.0f;
    if (init) {
        if (tid < DH) y_s[tid] = 0.0f;
    } else if (tid < DH) {
        y_s[tid] = d_st_y[cid * DH + tid];
        c_st = d_st_c[cid * DH + tid];
        n_st = d_st_n[cid * DH + tid];
        m_st = d_st_m[cid * DH + tid];
    }
    __syncthreads();
    cluster_barrier();                 // y_s visible cluster-wide before pulls

    const float* gbase = d_G + (size_t)cid * SS * 1024 + c * 128;
    float* ysb = d_ys + (size_t)cid * SS * DH;

    float g_cur = (tid < 128) ? __ldcg(gbase + (size_t)s0 * 1024 + tid) : 0.0f;

    uint32_t raw_base = smem_u32(&rawbuf[0][0]);

    // precomputed remote base addresses for this thread's pulls
    uint32_t pull_base[4];
    {
        int e = tid & 255;
        uint32_t la0 = raw_base + (uint32_t)((e & 127) * 4);
#pragma unroll
        for (int gg = 0; gg < 4; gg++)
            pull_base[gg] = mapa_rank(la0, (uint32_t)(gg * 2 + (e >> 7)));
    }

    // plain C++ pointer to this thread's 64-wide y slice (16B-aligned)
    const ulonglong2* ypair = (const ulonglong2*)(y_s + sub * 64);

    uint32_t par = 0;
    for (int s = s0; s < s1; s++) {
        // ---- matvec: 32 fma2 over this thread's 64 d-values ----
        // PLAIN loads: re-read y_s after each __syncthreads (fix for the
        // non-volatile-asm hoisting bug that broke v3/v5).
        unsigned long long a0 = 0ULL, a1 = 0ULL;
#pragma unroll
        for (int j = 0; j < 16; j++) {
            ulonglong2 p = ypair[j];        // {y[4j],y[4j+1]} , {y[4j+2],y[4j+3]}
            a0 = fma2(p.x, wv[2 * j],     a0);
            a1 = fma2(p.y, wv[2 * j + 1], a1);
        }
        float q0, q1, q2, q3;
        unpack2(a0, q0, q1);
        unpack2(a1, q2, q3);
        partial[sub][o_local] = (q0 + q1) + (q2 + q3);
        __syncthreads();

        if (tid < 128) {
            float r = partial[0][tid] + partial[1][tid] +
                      partial[2][tid] + partial[3][tid] + g_cur;
            rawbuf[par][tid] = r;
        }
        // prefetch next step's gate values (consumed next iteration)
        if (tid < 128 && s + 1 < SS)
            g_cur = __ldcg(gbase + (size_t)(s + 1) * 1024 + tid);

        // ---- v1-proven cluster barrier: publish raw, acquire peers' raw ----
        cluster_barrier();

        if (tid < DH) {
            uint32_t poff = par * 512;          // parity offset in bytes
            // batched pulls: all 4 issued before any dependent math (MLP=4)
            float r0 = ld_cluster_f32_addr(pull_base[0] + poff);
            float r1 = ld_cluster_f32_addr(pull_base[1] + poff);
            float r2 = ld_cluster_f32_addr(pull_base[2] + poff);
            float r3 = ld_cluster_f32_addr(pull_base[3] + poff);
            float ir = r0, fr = r1, zr = r2, orr = r3;
            // log_sigmoid(fr) = min(fr,0) - log1p(exp(-|fr|)), fast-math forms
            float ls  = fminf(fr, 0.0f) - __logf(1.0f + __expf(-fabsf(fr)));
            float lfm = m_st + ls;
            float mn  = fmaxf(ir, lfm);
            float ig  = __expf(ir - mn);
            float fg  = __expf(lfm - mn);
            float tz  = 1.0f - 2.0f * __fdividef(1.0f, __expf(2.0f * zr) + 1.0f);
            c_st = fg * c_st + ig * tz;
            n_st = fg * n_st + ig;
            m_st = mn;
            float sg = __fdividef(1.0f, 1.0f + __expf(-orr));
            float yv = sg * __fdividef(c_st, n_st);
            y_s[tid] = yv;
            if (c == 0) ysb[(size_t)s * DH + tid] = yv;
        }
        __syncthreads();
        par ^= 1;
    }

    // state handoff (all CTAs hold identical state; rank 0 writes)
    if (c == 0 && tid < DH && s1 < SS) {
        d_st_y[cid * DH + tid] = y_s[tid];
        d_st_c[cid * DH + tid] = c_st;
        d_st_n[cid * DH + tid] = n_st;
        d_st_m[cid * DH + tid] = m_st;
    }
    cluster_barrier();   // no CTA exits while peers may still pull its rawbuf
}

// ---------------------------------------------------------------------------
// Kernel 4: per-(b,h,s) GroupNorm over DH=256 + affine, write final output.
// ---------------------------------------------------------------------------
__global__ __launch_bounds__(256)
void groupnorm_kernel(const float* __restrict__ gn_scale,
                      const float* __restrict__ gn_bias,
                      float* __restrict__ out) {
    __shared__ float red_s[8];
    __shared__ float red_q[8];
    __shared__ float mu_sh, rs_sh;

    int row = blockIdx.x;              // cid*S + s
    int e   = threadIdx.x;
    int cid = row >> 11;
    int s   = row & (SS - 1);
    int b = cid >> 2, h = cid & 3;

    float v = d_ys[(size_t)row * DH + e];
    float sv = v, sq = v * v;
#pragma unroll
    for (int off = 16; off > 0; off >>= 1) {
        sv += __shfl_down_sync(0xFFFFFFFFu, sv, off);
        sq += __shfl_down_sync(0xFFFFFFFFu, sq, off);
    }
    int warp = e >> 5, lane = e & 31;
    if (lane == 0) { red_s[warp] = sv; red_q[warp] = sq; }
    __syncthreads();
    if (e == 0) {
        float ts = 0.f, tq = 0.f;
#pragma unroll
        for (int i = 0; i < 8; i++) { ts += red_s[i]; tq += red_q[i]; }
        float mu  = ts * (1.0f / DH);
        float var = tq * (1.0f / DH) - mu * mu;
        mu_sh = mu;
        rs_sh = rsqrtf(var + 1e-6f);
    }
    __syncthreads();
    int d = h * DH + e;
    float yn = (v - mu_sh) * rs_sh;
    out[((size_t)b * SS + s) * DD + d] = yn * gn_scale[d] + gn_bias[d];
}

// ---------------------------------------------------------------------------
// Launch: conv, gemm, scanA, scanB, gn  (5 launches per call)
// ---------------------------------------------------------------------------
extern "C" void kernel_launch(void* const* d_in, const int* in_sizes, int n_in,
                              void* d_out, int out_size) {
    const float* x        = (const float*)d_in[0];
    const float* convk    = (const float*)d_in[1];
    const float* convb    = (const float*)d_in[2];
    const float* w_i      = (const float*)d_in[3];
    const float* w_f      = (const float*)d_in[4];
    const float* w_z      = (const float*)d_in[5];
    const float* w_o      = (const float*)d_in[6];
    const float* rec_k    = (const float*)d_in[7];
    const float* rec_b    = (const float*)d_in[8];
    const float* gn_scale = (const float*)d_in[9];
    const float* gn_bias  = (const float*)d_in[10];
    float* out = (float*)d_out;

    size_t total = (size_t)BB * SS * DD;
    conv_swish_kernel<<<(unsigned)((total + 255) / 256), 256>>>(x, convk, convb);

    gemm_gates_kernel<<<16 * 128 * 4, 256>>>(x, w_i, w_f, w_z, w_o, rec_b);

    scan_kernel<<<NSEQ * CLN, 512>>>(rec_k, 0, SS / 2, 1);
    scan_kernel<<<NSEQ * CLN, 512>>>(rec_k, SS / 2, SS, 0);

    groupnorm_kernel<<<BB * NH * SS, 256>>>(gn_scale, gn_bias, out);
}

// round 17
// speedup vs baseline: 1.8425x; 1.0415x over previous
#include <cuda_runtime.h>
#include <cuda_bf16.h>
#include <cstdint>

// Problem constants
#define BB 4
#define SS 2048
#define DD 1024
#define NH 4
#define DH 256
#define NSEQ (BB*NH)          // 16 independent (b,h) sequences
#define CLN 8                 // CTAs per cluster in scan

// ---------------------------------------------------------------------------
// Scratch (device globals — no runtime allocation allowed)
// ---------------------------------------------------------------------------
__device__ float d_xconv[(size_t)BB*SS*DD];                // 33.5 MB
__device__ float d_G[(size_t)BB*NH*SS*4*DH];               // 134 MB  gates+rec_bias, [cid][s][g*256+e]
__device__ float d_ys[(size_t)BB*NH*SS*DH];                // 33.5 MB raw y before groupnorm
__device__ float d_st_y[NSEQ*DH];                          // scan state handoff
__device__ float d_st_c[NSEQ*DH];
__device__ float d_st_n[NSEQ*DH];
__device__ float d_st_m[NSEQ*DH];

// ---------------------------------------------------------------------------
// f32x2 + cluster helpers
// ---------------------------------------------------------------------------
__device__ __forceinline__ unsigned long long pack2(float lo, float hi) {
    unsigned long long d;
    asm("mov.b64 %0, {%1,%2};" : "=l"(d) : "f"(lo), "f"(hi));
    return d;
}
__device__ __forceinline__ unsigned long long fma2(unsigned long long a,
                                                   unsigned long long b,
                                                   unsigned long long c) {
    unsigned long long d;
    asm("fma.rn.f32x2 %0, %1, %2, %3;" : "=l"(d) : "l"(a), "l"(b), "l"(c));
    return d;
}
__device__ __forceinline__ void unpack2(unsigned long long d, float& lo, float& hi) {
    asm("mov.b64 {%0,%1}, %2;" : "=f"(lo), "=f"(hi) : "l"(d));
}
__device__ __forceinline__ uint32_t smem_u32(const void* p) {
    uint32_t a;
    asm("{ .reg .u64 t; cvta.to.shared.u64 t, %1; cvt.u32.u64 %0, t; }"
        : "=r"(a) : "l"(p));
    return a;
}
// cluster barrier (init/teardown only — NOT in the step loop anymore)
__device__ __forceinline__ void cluster_barrier() {
    asm volatile("barrier.cluster.arrive.aligned;" ::: "memory");
    asm volatile("barrier.cluster.wait.aligned;"   ::: "memory");
}
// remote arrive with RELEASE.CLUSTER semantics. The preceding __syncthreads
// gives HB from all producers' rawbuf STS to the arriving thread; the release
// makes them visible to the acquire-side waiter.
__device__ __forceinline__ void mbar_arrive_rank(uint32_t local_mbar, uint32_t rank) {
    uint32_t ra;
    asm("mapa.shared::cluster.u32 %0, %1, %2;" : "=r"(ra) : "r"(local_mbar), "r"(rank));
    asm volatile("mbarrier.arrive.release.cluster.shared::cluster.b64 _, [%0];"
                 :: "r"(ra) : "memory");
}
// ACQUIRE.CLUSTER parity wait — orders the subsequent generic
// ld.shared::cluster pulls against the producers' release-arrives.
__device__ __forceinline__ void mbar_wait_acq(uint32_t mbar, uint32_t parity) {
    uint32_t done;
    asm volatile(
        "{\n\t.reg .pred P;\n\t"
        "mbarrier.try_wait.parity.acquire.cluster.shared::cta.b64 P, [%1], %2, 0x989680;\n\t"
        "selp.b32 %0, 1, 0, P;\n\t}"
        : "=r"(done) : "r"(mbar), "r"(parity) : "memory");
    while (!done) {
        asm volatile(
            "{\n\t.reg .pred P;\n\t"
            "mbarrier.try_wait.parity.acquire.cluster.shared::cta.b64 P, [%1], %2, 0x989680;\n\t"
            "selp.b32 %0, 1, 0, P;\n\t}"
            : "=r"(done) : "r"(mbar), "r"(parity) : "memory");
    }
}
__device__ __forceinline__ uint32_t mapa_rank(uint32_t local_addr, uint32_t rank) {
    uint32_t ra;
    asm("mapa.shared::cluster.u32 %0, %1, %2;" : "=r"(ra) : "r"(local_addr), "r"(rank));
    return ra;
}
__device__ __forceinline__ float ld_cluster_f32_addr(uint32_t remote_addr) {
    float v;
    asm volatile("ld.shared::cluster.f32 %0, [%1];" : "=f"(v) : "r"(remote_addr));
    return v;
}

// ---------------------------------------------------------------------------
// Kernel 1: causal depthwise conv (K=4) + swish
// ---------------------------------------------------------------------------
__global__ void conv_swish_kernel(const float* __restrict__ x,
                                  const float* __restrict__ ck,
                                  const float* __restrict__ cb) {
    size_t idx = (size_t)blockIdx.x * blockDim.x + threadIdx.x;
    size_t total = (size_t)BB * SS * DD;
    if (idx >= total) return;
    int d = idx & (DD - 1);
    size_t bs = idx >> 10;
    int s = (int)(bs & (SS - 1));
    size_t b = bs >> 11;
    float acc = cb[d];
    const float* xb = x + b * (size_t)SS * DD + d;
#pragma unroll
    for (int k = 0; k < 4; k++) {
        int ss = s + k - 3;
        if (ss >= 0) acc = fmaf(xb[(size_t)ss * DD], ck[k * DD + d], acc);
    }
    float sig = 1.0f / (1.0f + __expf(-acc));
    d_xconv[idx] = acc * sig;
}

// ---------------------------------------------------------------------------
// Kernel 2: gate GEMMs (fp32, f32x2 FMA), smem double-buffered.
// ---------------------------------------------------------------------------
#define BM 64
#define BN 64
#define BK 16

__global__ __launch_bounds__(256)
void gemm_gates_kernel(const float* __restrict__ x,
                       const float* __restrict__ w_i, const float* __restrict__ w_f,
                       const float* __restrict__ w_z, const float* __restrict__ w_o,
                       const float* __restrict__ rec_bias) {
    __shared__ float As[2][BK][BM + 4];
    __shared__ float Bs[2][BK][BN + 8];

    int bx = blockIdx.x;
    int hg  = bx >> 9;           // 0..15
    int rem = bx & 511;
    int mt  = rem >> 2;          // 0..127
    int nt  = rem & 3;           // 0..3
    int h = hg >> 2, g = hg & 3;

    const float* A = (g < 2) ? d_xconv : x;
    const float* W = (g == 0) ? w_i : (g == 1) ? w_f : (g == 2) ? w_z : w_o;
    W += (size_t)h * DH * DH;
    int acol = h * DH;

    int tid = threadIdx.x;
    int a_m  = tid >> 2;
    int a_k4 = (tid & 3) << 2;
    int b_k  = tid >> 4;
    int b_n4 = (tid & 15) << 2;
    int ty = tid >> 4, tx = tid & 15;

    int m0 = mt * BM;
    const float* Aptr = A + (size_t)(m0 + a_m) * DD + acol + a_k4;
    const float* Wptr = W + (size_t)b_k * DH + nt * BN + b_n4;

    unsigned long long acc[4][2];
#pragma unroll
    for (int i = 0; i < 4; i++) { acc[i][0] = 0ULL; acc[i][1] = 0ULL; }

    {
        float4 av = *(const float4*)(Aptr);
        float4 bv = *(const float4*)(Wptr);
        As[0][a_k4 + 0][a_m] = av.x;
        As[0][a_k4 + 1][a_m] = av.y;
        As[0][a_k4 + 2][a_m] = av.z;
        As[0][a_k4 + 3][a_m] = av.w;
        *(float4*)&Bs[0][b_k][b_n4] = bv;
    }
    __syncthreads();

    int buf = 0;
    for (int k0 = 0; k0 < DH; k0 += BK) {
        bool more = (k0 + BK) < DH;
        float4 avn, bvn;
        if (more) {
            avn = *(const float4*)(Aptr + k0 + BK);
            bvn = *(const float4*)(Wptr + (size_t)(k0 + BK) * DH);
        }
#pragma unroll
        for (int k = 0; k < BK; k++) {
            float4 a4 = *(const float4*)&As[buf][k][ty * 4];
            float4 b4 = *(const float4*)&Bs[buf][k][tx * 4];
            unsigned long long b01 = pack2(b4.x, b4.y);
            unsigned long long b23 = pack2(b4.z, b4.w);
            float ar[4] = {a4.x, a4.y, a4.z, a4.w};
#pragma unroll
            for (int i = 0; i < 4; i++) {
                unsigned long long ad = pack2(ar[i], ar[i]);
                acc[i][0] = fma2(ad, b01, acc[i][0]);
                acc[i][1] = fma2(ad, b23, acc[i][1]);
            }
        }
        if (more) {
            int nb = buf ^ 1;
            As[nb][a_k4 + 0][a_m] = avn.x;
            As[nb][a_k4 + 1][a_m] = avn.y;
            As[nb][a_k4 + 2][a_m] = avn.z;
            As[nb][a_k4 + 3][a_m] = avn.w;
            *(float4*)&Bs[nb][b_k][b_n4] = bvn;
        }
        __syncthreads();
        buf ^= 1;
    }

    int n = nt * BN + tx * 4;
    const float* rb = rec_bias + (g * NH + h) * DH + n;
    float rb0 = rb[0], rb1 = rb[1], rb2 = rb[2], rb3 = rb[3];
#pragma unroll
    for (int i = 0; i < 4; i++) {
        int m = m0 + ty * 4 + i;
        int b = m >> 11;
        int s = m & (SS - 1);
        float o0, o1, o2, o3;
        unpack2(acc[i][0], o0, o1);
        unpack2(acc[i][1], o2, o3);
        float4 outv = make_float4(o0 + rb0, o1 + rb1, o2 + rb2, o3 + rb3);
        size_t gidx = (((size_t)(b * NH + h) * SS + s) << 10) + g * DH + n;
        *(float4*)&d_G[gidx] = outv;
    }
}

// ---------------------------------------------------------------------------
// Kernel 3: sequential sLSTM scan, v7 = v6 with the per-step cluster_barrier
// replaced by PING-PONG release/acquire mbarriers (the measured v1->v6 delta
// shows the step is sync-bound, not compute-bound; barrier.cluster's ~490cyc
// UCGABAR wait + CCTL.IVALL flush is the target).
// Two mbarriers alternate by step parity so a fast CTA's step-(t+1) arrivals
// can never land in a peer's still-open step-t phase (over-arrival hazard).
// Per step:
//   matvec (fma2, plain loads) -> STS partial -> __syncthreads
//   -> tid<128: raw -> rawbuf[t&1] -> __syncthreads (HB for arrivers)
//   -> tid 256..263: one release.cluster arrive each on mbar[t&1] of rank tid-256
//   -> tid<128: prefetch next gate input (overlaps wait)
//   -> all: acquire.cluster parity wait on local mbar[t&1], parity (t>>1)&1
//   -> tid<256: batched pulls, fast-math update, y_s store; rank 0 -> gmem
//   -> __syncthreads.
// ---------------------------------------------------------------------------
__global__ void __launch_bounds__(512, 1) __cluster_dims__(CLN, 1, 1)
scan_kernel(const float* __restrict__ rk, int s0, int s1, int init) {
    __shared__ __align__(16) float y_s[DH];
    __shared__ float partial[4][128];
    __shared__ float rawbuf[2][128];
    __shared__ __align__(8) unsigned long long mbar[2];

    int tid = threadIdx.x;
    int c   = blockIdx.x & (CLN - 1);
    int cid = blockIdx.x >> 3;              // b*NH + h
    int h   = cid & (NH - 1);

    int o_local = tid & 127;
    int sub     = tid >> 7;                 // 0..3
    int o  = c * 128 + o_local;
    int g  = o >> 8;
    int eo = o & 255;

    // ---- 64 weights as 32 f32x2 pairs: d in [sub*64, sub*64+64) ----
    unsigned long long wv[32];
    {
        const float* wp = rk + (((size_t)h * DH + sub * 64) * 4 + g) * DH + eo;
#pragma unroll
        for (int k = 0; k < 32; k++) {
            float lo = __ldcg(wp + (size_t)(2 * k)     * 4 * DH);
            float hi = __ldcg(wp + (size_t)(2 * k + 1) * 4 * DH);
            wv[k] = pack2(lo, hi);
        }
    }

    float c_st = 0.0f, n_st = 0.0f, m_st = 0.0f;
    if (init) {
        if (tid < DH) y_s[tid] = 0.0f;
    } else if (tid < DH) {
        y_s[tid] = d_st_y[cid * DH + tid];
        c_st = d_st_c[cid * DH + tid];
        n_st = d_st_n[cid * DH + tid];
        m_st = d_st_m[cid * DH + tid];
    }
    uint32_t mb_base = smem_u32(&mbar[0]);
    if (tid == 0) {
        asm volatile("mbarrier.init.shared.b64 [%0], %1;" :: "r"(mb_base),     "r"(CLN) : "memory");
        asm volatile("mbarrier.init.shared.b64 [%0], %1;" :: "r"(mb_base + 8), "r"(CLN) : "memory");
    }
    __syncthreads();
    cluster_barrier();   // mbarriers + y_s visible cluster-wide before any arrive/pull

    const float* gbase = d_G + (size_t)cid * SS * 1024 + c * 128;
    float* ysb = d_ys + (size_t)cid * SS * DH;

    float g_cur = (tid < 128) ? __ldcg(gbase + (size_t)s0 * 1024 + tid) : 0.0f;

    uint32_t raw_base = smem_u32(&rawbuf[0][0]);

    // precomputed remote base addresses for this thread's pulls
    uint32_t pull_base[4];
    {
        int e = tid & 255;
        uint32_t la0 = raw_base + (uint32_t)((e & 127) * 4);
#pragma unroll
        for (int gg = 0; gg < 4; gg++)
            pull_base[gg] = mapa_rank(la0, (uint32_t)(gg * 2 + (e >> 7)));
    }

    // plain C++ pointer to this thread's 64-wide y slice (16B-aligned)
    const ulonglong2* ypair = (const ulonglong2*)(y_s + sub * 64);

    uint32_t t = 0;                          // step counter within this launch
    for (int s = s0; s < s1; s++, t++) {
        uint32_t par = t & 1;                // rawbuf + mbarrier select
        uint32_t ph  = (t >> 1) & 1;         // phase parity of mbar[par]

        // ---- matvec: 32 fma2 over this thread's 64 d-values ----
        unsigned long long a0 = 0ULL, a1 = 0ULL;
#pragma unroll
        for (int j = 0; j < 16; j++) {
            ulonglong2 p = ypair[j];
            a0 = fma2(p.x, wv[2 * j],     a0);
            a1 = fma2(p.y, wv[2 * j + 1], a1);
        }
        float q0, q1, q2, q3;
        unpack2(a0, q0, q1);
        unpack2(a1, q2, q3);
        partial[sub][o_local] = (q0 + q1) + (q2 + q3);
        __syncthreads();

        if (tid < 128) {
            float r = partial[0][tid] + partial[1][tid] +
                      partial[2][tid] + partial[3][tid] + g_cur;
            rawbuf[par][tid] = r;
        }
        __syncthreads();            // HB: all rawbuf STS -> the arriving threads

        // warp 8 (no pull/prefetch duties): one release arrive per rank
        if (tid >= 256 && tid < 256 + CLN)
            mbar_arrive_rank(mb_base + par * 8, (uint32_t)(tid - 256));

        // prefetch next step's gate values during the wait window
        if (tid < 128 && s + 1 < SS)
            g_cur = __ldcg(gbase + (size_t)(s + 1) * 1024 + tid);

        mbar_wait_acq(mb_base + par * 8, ph);

        if (tid < DH) {
            uint32_t poff = par * 512;          // rawbuf parity offset in bytes
            float r0 = ld_cluster_f32_addr(pull_base[0] + poff);
            float r1 = ld_cluster_f32_addr(pull_base[1] + poff);
            float r2 = ld_cluster_f32_addr(pull_base[2] + poff);
            float r3 = ld_cluster_f32_addr(pull_base[3] + poff);
            float ir = r0, fr = r1, zr = r2, orr = r3;
            float ls  = fminf(fr, 0.0f) - __logf(1.0f + __expf(-fabsf(fr)));
            float lfm = m_st + ls;
            float mn  = fmaxf(ir, lfm);
            float ig  = __expf(ir - mn);
            float fg  = __expf(lfm - mn);
            float tz  = 1.0f - 2.0f * __fdividef(1.0f, __expf(2.0f * zr) + 1.0f);
            c_st = fg * c_st + ig * tz;
            n_st = fg * n_st + ig;
            m_st = mn;
            float sg = __fdividef(1.0f, 1.0f + __expf(-orr));
            float yv = sg * __fdividef(c_st, n_st);
            y_s[tid] = yv;
            if (c == 0) ysb[(size_t)s * DH + tid] = yv;
        }
        __syncthreads();
    }

    // state handoff (all CTAs hold identical state; rank 0 writes)
    if (c == 0 && tid < DH && s1 < SS) {
        d_st_y[cid * DH + tid] = y_s[tid];
        d_st_c[cid * DH + tid] = c_st;
        d_st_n[cid * DH + tid] = n_st;
        d_st_m[cid * DH + tid] = m_st;
    }
    cluster_barrier();   // no CTA exits while peers may still pull its rawbuf
}

// ---------------------------------------------------------------------------
// Kernel 4: per-(b,h,s) GroupNorm over DH=256 + affine, write final output.
// ---------------------------------------------------------------------------
__global__ __launch_bounds__(256)
void groupnorm_kernel(const float* __restrict__ gn_scale,
                      const float* __restrict__ gn_bias,
                      float* __restrict__ out) {
    __shared__ float red_s[8];
    __shared__ float red_q[8];
    __shared__ float mu_sh, rs_sh;

    int row = blockIdx.x;              // cid*S + s
    int e   = threadIdx.x;
    int cid = row >> 11;
    int s   = row & (SS - 1);
    int b = cid >> 2, h = cid & 3;

    float v = d_ys[(size_t)row * DH + e];
    float sv = v, sq = v * v;
#pragma unroll
    for (int off = 16; off > 0; off >>= 1) {
        sv += __shfl_down_sync(0xFFFFFFFFu, sv, off);
        sq += __shfl_down_sync(0xFFFFFFFFu, sq, off);
    }
    int warp = e >> 5, lane = e & 31;
    if (lane == 0) { red_s[warp] = sv; red_q[warp] = sq; }
    __syncthreads();
    if (e == 0) {
        float ts = 0.f, tq = 0.f;
#pragma unroll
        for (int i = 0; i < 8; i++) { ts += red_s[i]; tq += red_q[i]; }
        float mu  = ts * (1.0f / DH);
        float var = tq * (1.0f / DH) - mu * mu;
        mu_sh = mu;
        rs_sh = rsqrtf(var + 1e-6f);
    }
    __syncthreads();
    int d = h * DH + e;
    float yn = (v - mu_sh) * rs_sh;
    out[((size_t)b * SS + s) * DD + d] = yn * gn_scale[d] + gn_bias[d];
}

// ---------------------------------------------------------------------------
// Launch: conv, gemm, scanA, scanB, gn  (5 launches per call)
// ---------------------------------------------------------------------------
extern "C" void kernel_launch(void* const* d_in, const int* in_sizes, int n_in,
                              void* d_out, int out_size) {
    const float* x        = (const float*)d_in[0];
    const float* convk    = (const float*)d_in[1];
    const float* convb    = (const float*)d_in[2];
    const float* w_i      = (const float*)d_in[3];
    const float* w_f      = (const float*)d_in[4];
    const float* w_z      = (const float*)d_in[5];
    const float* w_o      = (const float*)d_in[6];
    const float* rec_k    = (const float*)d_in[7];
    const float* rec_b    = (const float*)d_in[8];
    const float* gn_scale = (const float*)d_in[9];
    const float* gn_bias  = (const float*)d_in[10];
    float* out = (float*)d_out;

    size_t total = (size_t)BB * SS * DD;
    conv_swish_kernel<<<(unsigned)((total + 255) / 256), 256>>>(x, convk, convb);

    gemm_gates_kernel<<<16 * 128 * 4, 256>>>(x, w_i, w_f, w_z, w_o, rec_b);

    scan_kernel<<<NSEQ * CLN, 512>>>(rec_k, 0, SS / 2, 1);
    scan_kernel<<<NSEQ * CLN, 512>>>(rec_k, SS / 2, SS, 0);

    groupnorm_kernel<<<BB * NH * SS, 256>>>(gn_scale, gn_bias, out);
}